// round 12
// baseline (speedup 1.0000x reference)
#include <cuda_runtime.h>
#include <cstdint>

#define BN 1024
#define VN 6890
#define JN 24
#define KF 207            // (J-1)*9
#define NV3 (VN*3)        // 20670

#define OFF_VERTS  0
#define OFF_JPOSED (BN*VN*3)
#define OFF_JREST  (OFF_JPOSED + BN*JN*3)
#define OFF_A      (OFF_JREST + BN*JN*3)
#define OFF_VSH    (OFF_A + BN*JN*16)

// ---- k_vertex dynamic smem layout (bytes) ----
#define S_A_OFF   0                 // float[24][12][16] = 18432
#define S_B_OFF   18432             // float[10][16]     = 640
#define S_VP_OFF  19072             // ull[128][25]      = 25600
#define S_W_OFF   44672             // float[128][25]    = 12800
#define SMEM_BYTES 57472

__device__ float g_vp[(long)NV3 * BN];   // pose-blend delta, [m][b]  (84.7 MB scratch)
__device__ float g_pf[BN*KF];            // pose_feature [b][k]
__device__ float g_JS[72*10];
__device__ float g_JT[72];
__device__ float g_part[72*8*11];

typedef unsigned long long ull;

__device__ __forceinline__ ull pack2(float x, float y){
    ull r; asm("mov.b64 %0, {%1,%2};" : "=l"(r) : "f"(x), "f"(y)); return r;
}
__device__ __forceinline__ ull fma2(ull a, ull b, ull c){
    ull d; asm("fma.rn.f32x2 %0, %1, %2, %3;" : "=l"(d) : "l"(a), "l"(b), "l"(c)); return d;
}
__device__ __forceinline__ ull add2(ull a, ull b){
    ull d; asm("add.rn.f32x2 %0, %1, %2;" : "=l"(d) : "l"(a), "l"(b)); return d;
}
__device__ __forceinline__ void unpack2(ull v, float& x, float& y){
    asm("mov.b64 {%0,%1}, %2;" : "=f"(x), "=f"(y) : "l"(v));
}
__device__ __forceinline__ uint32_t to_tf32(float x){
    uint32_t t; asm("cvt.rna.tf32.f32 %0, %1;" : "=r"(t) : "f"(x)); return t;
}

// ---------------------------------------------------------------------------
// Kernel 1a/1b: joint-regressor precompute (partials + deterministic combine)
// ---------------------------------------------------------------------------
__global__ void __launch_bounds__(256) k_reg_part(
    const float* __restrict__ Jreg, const float* __restrict__ sdirs,
    const float* __restrict__ vt)
{
    const int jc = blockIdx.x;
    const int j = jc / 3, c = jc % 3;
    const int v0 = blockIdx.y * 862;
    const int v1 = (v0 + 862 < VN) ? v0 + 862 : VN;
    float acc[11];
#pragma unroll
    for (int l = 0; l < 11; l++) acc[l] = 0.f;
    for (int v = v0 + threadIdx.x; v < v1; v += 256){
        float r = Jreg[j*VN + v];
        const float* sd = sdirs + (v*3 + c)*10;
#pragma unroll
        for (int l = 0; l < 10; l++) acc[l] += r * __ldg(sd + l);
        acc[10] += r * vt[v*3 + c];
    }
    __shared__ float red[11][256];
#pragma unroll
    for (int l = 0; l < 11; l++) red[l][threadIdx.x] = acc[l];
    __syncthreads();
    for (int s = 128; s > 0; s >>= 1){
        if (threadIdx.x < s){
#pragma unroll
            for (int l = 0; l < 11; l++)
                red[l][threadIdx.x] += red[l][threadIdx.x + s];
        }
        __syncthreads();
    }
    if (threadIdx.x == 0){
#pragma unroll
        for (int l = 0; l < 11; l++)
            g_part[(jc*8 + blockIdx.y)*11 + l] = red[l][0];
    }
}

__global__ void k_reg_fin()
{
    int t = threadIdx.x;
    if (t < 72){
        float s[11];
#pragma unroll
        for (int l = 0; l < 11; l++) s[l] = 0.f;
        for (int q = 0; q < 8; q++)
#pragma unroll
            for (int l = 0; l < 11; l++)
                s[l] += g_part[(t*8 + q)*11 + l];
#pragma unroll
        for (int l = 0; l < 10; l++) g_JS[t*10 + l] = s[l];
        g_JT[t] = s[10];
    }
}

// ---------------------------------------------------------------------------
// Kernel 2: per-batch joints (Rodrigues, chain, A)
// ---------------------------------------------------------------------------
__global__ void __launch_bounds__(256) k_joints(
    const float* __restrict__ betas, const float* __restrict__ pose,
    const int* __restrict__ parents, float* __restrict__ out)
{
    __shared__ float sL[8][24][12];
    __shared__ float sW[8][24][12];
    __shared__ int   s_par[24];
    const int w = threadIdx.x >> 5, lane = threadIdx.x & 31;
    const int b = blockIdx.x * 8 + w;
    if (threadIdx.x < 24) s_par[threadIdx.x] = parents[threadIdx.x];
    __syncthreads();

    const int j = lane;
    float Jr0 = 0.f, Jr1 = 0.f, Jr2 = 0.f;

    if (j < JN){
        float x = pose[b*72 + j*3 + 0];
        float y = pose[b*72 + j*3 + 1];
        float z = pose[b*72 + j*3 + 2];
        float ax = x + 1e-8f, ay = y + 1e-8f, az = z + 1e-8f;
        float ang = sqrtf(ax*ax + ay*ay + az*az);
        float inv = 1.0f / ang;
        float kx = x*inv, ky = y*inv, kz = z*inv;
        float sn = sinf(ang), cs = cosf(ang);
        float oc = 1.0f - cs;
        float kk = kx*kx + ky*ky + kz*kz;
        float R[9];
        R[0] = 1.f + oc*(kx*kx - kk);  R[1] = -sn*kz + oc*kx*ky;      R[2] =  sn*ky + oc*kx*kz;
        R[3] =  sn*kz + oc*ky*kx;      R[4] = 1.f + oc*(ky*ky - kk);  R[5] = -sn*kx + oc*ky*kz;
        R[6] = -sn*ky + oc*kz*kx;      R[7] =  sn*kx + oc*kz*ky;      R[8] = 1.f + oc*(kz*kz - kk);

        float jr[3];
#pragma unroll
        for (int c = 0; c < 3; c++){
            float a = g_JT[j*3 + c];
#pragma unroll
            for (int l = 0; l < 10; l++)
                a += betas[b*10 + l] * g_JS[(j*3+c)*10 + l];
            jr[c] = a;
            out[OFF_JREST + b*JN*3 + j*3 + c] = a;
        }
        Jr0 = jr[0]; Jr1 = jr[1]; Jr2 = jr[2];

        if (j >= 1){
            float* pf = g_pf + b*KF + (j-1)*9;
#pragma unroll
            for (int r = 0; r < 3; r++)
#pragma unroll
                for (int c = 0; c < 3; c++)
                    pf[r*3 + c] = R[r*3 + c] - ((r == c) ? 1.f : 0.f);
        }
#pragma unroll
        for (int r = 0; r < 3; r++){
            sL[w][j][r*4+0] = R[r*3+0];
            sL[w][j][r*4+1] = R[r*3+1];
            sL[w][j][r*4+2] = R[r*3+2];
        }
    }

    int par = 0;
    if (j < JN && j > 0) par = s_par[j];
    float p0 = __shfl_sync(0xffffffffu, Jr0, par);
    float p1 = __shfl_sync(0xffffffffu, Jr1, par);
    float p2 = __shfl_sync(0xffffffffu, Jr2, par);
    if (j < JN){
        sL[w][j][3]  = (j == 0) ? Jr0 : Jr0 - p0;
        sL[w][j][7]  = (j == 0) ? Jr1 : Jr1 - p1;
        sL[w][j][11] = (j == 0) ? Jr2 : Jr2 - p2;
    }
    __syncwarp();

    if (lane < 12) sW[w][0][lane] = sL[w][0][lane];
    __syncwarp();
    for (int i = 1; i < JN; i++){
        if (lane < 12){
            int pi = s_par[i];
            const float* Wp = sW[w][pi];
            const float* L  = sL[w][i];
            int r = lane >> 2, cc = lane & 3;
            float val = Wp[r*4+0]*L[0*4+cc] + Wp[r*4+1]*L[1*4+cc] + Wp[r*4+2]*L[2*4+cc];
            if (cc == 3) val += Wp[r*4+3];
            sW[w][i][lane] = val;
        }
        __syncwarp();
    }

    if (j < JN){
        const float* W = sW[w][j];
#pragma unroll
        for (int r = 0; r < 3; r++)
            out[OFF_JPOSED + b*JN*3 + j*3 + r] = W[r*4+3];
        float* Ao = out + OFF_A + (b*JN + j)*16;
#pragma unroll
        for (int r = 0; r < 3; r++){
            Ao[r*4+0] = W[r*4+0]; Ao[r*4+1] = W[r*4+1]; Ao[r*4+2] = W[r*4+2];
            Ao[r*4+3] = W[r*4+3] - (W[r*4+0]*Jr0 + W[r*4+1]*Jr1 + W[r*4+2]*Jr2);
        }
        Ao[12] = 0.f; Ao[13] = 0.f; Ao[14] = 0.f; Ao[15] = 1.f;
    }
}

// ---------------------------------------------------------------------------
// Kernel 3: pose-blend GEMM on tensor cores (tf32 HMMA).
//   delta[m][n] = sum_k pdirs[k][m] * pf[n][k],  m in [0,20670), n in [0,1024)
//   Block tile 128(M) x 64(N) x 8(K); 8 warps as 4(M) x 2(N); warp 32x32.
// ---------------------------------------------------------------------------
#define GBM 128
#define GBN 64
#define GBK 8
#define KSTEPS 26        // 26*8 = 208 >= 207 (tail zero-padded)
#define SA_LD 136        // padded: k-row bank offsets 0/8/16/24 -> conflict-free
#define SB_LD 72

__global__ void __launch_bounds__(256) k_gemm(const float* __restrict__ pdirs)
{
    __shared__ uint32_t sA[GBK][SA_LD];
    __shared__ uint32_t sB[GBK][SB_LD];
    const int tid = threadIdx.x;
    const int warp = tid >> 5, lane = tid & 31;
    const int m0 = blockIdx.x * GBM;
    const int n0 = blockIdx.y * GBN;
    const int wm = (warp & 3) * 32;
    const int wn = (warp >> 2) * 32;
    const int g  = lane >> 2, tg = lane & 3;

    float d[2][4][4];
#pragma unroll
    for (int mt = 0; mt < 2; mt++)
#pragma unroll
        for (int nt = 0; nt < 4; nt++)
#pragma unroll
            for (int i = 0; i < 4; i++) d[mt][nt][i] = 0.f;

    for (int ks = 0; ks < KSTEPS; ks++){
        const int k0 = ks * GBK;
        __syncthreads();
        // stage A (pdirs[k][m] -> sA[k][m]), coalesced, zero-padded
#pragma unroll
        for (int i = 0; i < 4; i++){
            int idx = tid + i*256;
            int kk = idx >> 7, mm = idx & 127;
            int gk = k0 + kk, gm = m0 + mm;
            float val = (gk < KF && gm < NV3) ? __ldg(pdirs + (long)gk*NV3 + gm) : 0.f;
            sA[kk][mm] = to_tf32(val);
        }
        // stage B (pf[n][k] -> sB[k][n])
#pragma unroll
        for (int i = 0; i < 2; i++){
            int idx = tid + i*256;
            int nn = idx >> 3, kk = idx & 7;
            int gk = k0 + kk;
            float val = (gk < KF) ? __ldg(g_pf + (n0 + nn)*KF + gk) : 0.f;
            sB[kk][nn] = to_tf32(val);
        }
        __syncthreads();

        uint32_t a[2][4], bf[4][2];
#pragma unroll
        for (int mt = 0; mt < 2; mt++){
            int rb = wm + mt*16 + g;
            a[mt][0] = sA[tg  ][rb];
            a[mt][1] = sA[tg  ][rb+8];
            a[mt][2] = sA[tg+4][rb];
            a[mt][3] = sA[tg+4][rb+8];
        }
#pragma unroll
        for (int nt = 0; nt < 4; nt++){
            int cb = wn + nt*8 + g;
            bf[nt][0] = sB[tg  ][cb];
            bf[nt][1] = sB[tg+4][cb];
        }
#pragma unroll
        for (int mt = 0; mt < 2; mt++)
#pragma unroll
            for (int nt = 0; nt < 4; nt++){
                asm volatile(
                    "mma.sync.aligned.m16n8k8.row.col.f32.tf32.tf32.f32 "
                    "{%0,%1,%2,%3}, {%4,%5,%6,%7}, {%8,%9}, {%0,%1,%2,%3};"
                    : "+f"(d[mt][nt][0]), "+f"(d[mt][nt][1]),
                      "+f"(d[mt][nt][2]), "+f"(d[mt][nt][3])
                    : "r"(a[mt][0]), "r"(a[mt][1]), "r"(a[mt][2]), "r"(a[mt][3]),
                      "r"(bf[nt][0]), "r"(bf[nt][1]));
            }
    }

    // epilogue: D rows = m, cols = n(batch); g_vp layout [m][1024]
#pragma unroll
    for (int mt = 0; mt < 2; mt++)
#pragma unroll
        for (int nt = 0; nt < 4; nt++){
            int r0 = m0 + wm + mt*16 + g;
            int c0 = n0 + wn + nt*8 + tg*2;
            if (r0 < NV3)
                *(float2*)(g_vp + (long)r0*BN + c0) = make_float2(d[mt][nt][0], d[mt][nt][1]);
            if (r0 + 8 < NV3)
                *(float2*)(g_vp + (long)(r0+8)*BN + c0) = make_float2(d[mt][nt][2], d[mt][nt][3]);
        }
}

// ---------------------------------------------------------------------------
// Kernel 4: vertex kernel. Block = 128 vertices x 16 batches.
//  Phase 1: shape blend (+v_shaped out) + GEMM delta add -> v_posed.
//  Phase 2: skinning; warp = one batch-pair, A loads broadcast.
// ---------------------------------------------------------------------------
__global__ void __launch_bounds__(256, 3) k_vertex(
    const float* __restrict__ betas, const float* __restrict__ vt,
    const float* __restrict__ sdirs, const float* __restrict__ lbsw,
    float* __restrict__ out)
{
    extern __shared__ char smem[];
    float (*s_A)[12][16] = (float(*)[12][16])(smem + S_A_OFF);
    float (*s_b)[16]     = (float(*)[16])(smem + S_B_OFF);
    ull   (*s_vp)[25]    = (ull(*)[25])(smem + S_VP_OFF);
    float (*s_w)[25]     = (float(*)[25])(smem + S_W_OFF);

    const int tid = threadIdx.x;
    const int b_block = blockIdx.y * 16;
    const int v_base  = blockIdx.x * 128;

    for (int idx = tid; idx < 16*JN*12; idx += 256){
        int bi = idx / 288, e = idx - bi*288;
        int j = e / 12, rc = e - j*12;
        s_A[j][rc][bi] = out[OFF_A + ((b_block + bi)*JN + j)*16 + rc];
    }
    for (int idx = tid; idx < 160; idx += 256){
        int bi = idx / 10, l = idx - bi*10;
        s_b[l][bi] = betas[(b_block + bi)*10 + l];
    }
    for (int idx = tid; idx < 128*JN; idx += 256){
        int vl = idx / JN, j = idx - vl*JN;
        int vg = v_base + vl; if (vg >= VN) vg = VN - 1;
        s_w[vl][j] = lbsw[vg*JN + j];
    }
    __syncthreads();

    // ---- phase 1 ----
    const int v_loc = tid >> 1;
    const int half  = tid & 1;
    const int bb    = half * 8;
    const int v     = v_base + v_loc;
    const bool valid = v < VN;
    const int vv = valid ? v : (VN - 1);

    ull acc[4][3];
    {
        float t0 = vt[vv*3+0], t1 = vt[vv*3+1], t2 = vt[vv*3+2];
        ull d0 = pack2(t0,t0), d1 = pack2(t1,t1), d2 = pack2(t2,t2);
#pragma unroll
        for (int p = 0; p < 4; p++){ acc[p][0]=d0; acc[p][1]=d1; acc[p][2]=d2; }
    }
    {
        const float* sd = sdirs + vv*30;
#pragma unroll
        for (int l = 0; l < 10; l++){
            float a0 = __ldg(sd + l), a1 = __ldg(sd + 10 + l), a2 = __ldg(sd + 20 + l);
            ull d0 = pack2(a0,a0), d1 = pack2(a1,a1), d2 = pack2(a2,a2);
            const ull* bl = (const ull*)&s_b[l][bb];
#pragma unroll
            for (int p = 0; p < 4; p++){
                ull bp = bl[p];
                acc[p][0] = fma2(d0, bp, acc[p][0]);
                acc[p][1] = fma2(d1, bp, acc[p][1]);
                acc[p][2] = fma2(d2, bp, acc[p][2]);
            }
        }
    }
    if (valid){
#pragma unroll
        for (int p = 0; p < 4; p++){
            int b0 = b_block + bb + 2*p;
            float x, y;
            unpack2(acc[p][0], x, y);
            out[OFF_VSH + b0*NV3 + v*3+0] = x; out[OFF_VSH + (b0+1)*NV3 + v*3+0] = y;
            unpack2(acc[p][1], x, y);
            out[OFF_VSH + b0*NV3 + v*3+1] = x; out[OFF_VSH + (b0+1)*NV3 + v*3+1] = y;
            unpack2(acc[p][2], x, y);
            out[OFF_VSH + b0*NV3 + v*3+2] = x; out[OFF_VSH + (b0+1)*NV3 + v*3+2] = y;
        }
    }

    // add pose-blend delta from tensor-core GEMM: g_vp[m][b], 8 batches/coord
#pragma unroll
    for (int c = 0; c < 3; c++){
        const ulonglong2* dp = (const ulonglong2*)(g_vp + ((long)vv*3 + c)*BN + b_block + bb);
        ulonglong2 q0 = __ldg(dp), q1 = __ldg(dp + 1);
        acc[0][c] = add2(acc[0][c], q0.x);
        acc[1][c] = add2(acc[1][c], q0.y);
        acc[2][c] = add2(acc[2][c], q1.x);
        acc[3][c] = add2(acc[3][c], q1.y);
    }

    // ---- handoff to smem ----
#pragma unroll
    for (int p = 0; p < 4; p++){
        int pair = half*4 + p;
        s_vp[v_loc][pair*3 + 0] = acc[p][0];
        s_vp[v_loc][pair*3 + 1] = acc[p][1];
        s_vp[v_loc][pair*3 + 2] = acc[p][2];
    }
    __syncthreads();

    // ---- phase 2: skinning. 8 pairs x 32 lanes; lane owns 4 vertices ----
    const int pp = tid >> 5;
    const int l  = tid & 31;

    ull vp[4][3], vr[4][3];
#pragma unroll
    for (int i = 0; i < 4; i++){
#pragma unroll
        for (int c = 0; c < 3; c++){
            vp[i][c] = s_vp[l + 32*i][pp*3 + c];
            vr[i][c] = 0ull;
        }
    }

#pragma unroll 4
    for (int j = 0; j < JN; j++){
        ull ar[12];
#pragma unroll
        for (int rc = 0; rc < 12; rc++)
            ar[rc] = *(const ull*)&s_A[j][rc][2*pp];   // warp-broadcast
#pragma unroll
        for (int i = 0; i < 4; i++){
            float wj = s_w[l + 32*i][j];
            ull w2 = pack2(wj, wj);
            ull vx = vp[i][0], vy = vp[i][1], vz = vp[i][2];
#pragma unroll
            for (int r = 0; r < 3; r++){
                ull q = fma2(ar[r*4+2], vz, ar[r*4+3]);
                q     = fma2(ar[r*4+1], vy, q);
                q     = fma2(ar[r*4+0], vx, q);
                vr[i][r] = fma2(w2, q, vr[i][r]);
            }
        }
    }

    const int b0 = b_block + 2*pp;
#pragma unroll
    for (int i = 0; i < 4; i++){
        int vg = v_base + l + 32*i;
        if (vg < VN){
            float x, y;
            unpack2(vr[i][0], x, y);
            out[OFF_VERTS + b0*NV3 + vg*3+0] = x; out[OFF_VERTS + (b0+1)*NV3 + vg*3+0] = y;
            unpack2(vr[i][1], x, y);
            out[OFF_VERTS + b0*NV3 + vg*3+1] = x; out[OFF_VERTS + (b0+1)*NV3 + vg*3+1] = y;
            unpack2(vr[i][2], x, y);
            out[OFF_VERTS + b0*NV3 + vg*3+2] = x; out[OFF_VERTS + (b0+1)*NV3 + vg*3+2] = y;
        }
    }
}

extern "C" void kernel_launch(void* const* d_in, const int* in_sizes, int n_in,
                              void* d_out, int out_size)
{
    const float* betas   = (const float*)d_in[0];
    const float* pose    = (const float*)d_in[1];
    const float* vt      = (const float*)d_in[2];
    const float* sdirs   = (const float*)d_in[3];
    const float* pdirs   = (const float*)d_in[4];
    const float* Jreg    = (const float*)d_in[5];
    const float* lbsw    = (const float*)d_in[6];
    const int*   parents = (const int*)d_in[7];
    float* out = (float*)d_out;

    cudaFuncSetAttribute(k_vertex, cudaFuncAttributeMaxDynamicSharedMemorySize, SMEM_BYTES);

    dim3 g1(72, 8);
    k_reg_part<<<g1, 256>>>(Jreg, sdirs, vt);
    k_reg_fin<<<1, 128>>>();
    k_joints<<<128, 256>>>(betas, pose, parents, out);
    dim3 gg((NV3 + GBM - 1)/GBM, BN/GBN);   // 162 x 16
    k_gemm<<<gg, 256>>>(pdirs);
    dim3 g3(54, 64);   // ceil(6890/128) x (1024/16)
    k_vertex<<<g3, 256, SMEM_BYTES>>>(betas, vt, sdirs, lbsw, out);
}

// round 14
// speedup vs baseline: 1.1110x; 1.1110x over previous
#include <cuda_runtime.h>
#include <cstdint>

#define BN 1024
#define VN 6890
#define JN 24
#define KF 207            // (J-1)*9
#define NV3 (VN*3)        // 20670

#define OFF_VERTS  0
#define OFF_JPOSED (BN*VN*3)
#define OFF_JREST  (OFF_JPOSED + BN*JN*3)
#define OFF_A      (OFF_JREST + BN*JN*3)
#define OFF_VSH    (OFF_A + BN*JN*16)

// ---- k_vertex dynamic smem layout (bytes) ----
#define S_A_OFF   0                 // float[24][12][16] = 18432
#define S_B_OFF   18432             // float[10][16]     = 640
#define S_VP_OFF  19072             // ull[128][25]      = 25600
#define S_W_OFF   44672             // float[128][25]    = 12800
#define SMEM_BYTES 57472

#define KP2 224                     // 7 * 32, zero-padded K for the GEMM

__device__ __align__(16) float g_vp[(long)NV3 * BN];   // pose-blend delta, [m][b]
__device__ __align__(16) float g_pfT[KP2 * BN];        // pose_feature [k][b]; rows>=207 stay 0
__device__ float g_JS[72*10];
__device__ float g_JT[72];
__device__ float g_part[72*8*11];

typedef unsigned long long ull;

__device__ __forceinline__ ull pack2(float x, float y){
    ull r; asm("mov.b64 %0, {%1,%2};" : "=l"(r) : "f"(x), "f"(y)); return r;
}
__device__ __forceinline__ ull fma2(ull a, ull b, ull c){
    ull d; asm("fma.rn.f32x2 %0, %1, %2, %3;" : "=l"(d) : "l"(a), "l"(b), "l"(c)); return d;
}
__device__ __forceinline__ ull add2(ull a, ull b){
    ull d; asm("add.rn.f32x2 %0, %1, %2;" : "=l"(d) : "l"(a), "l"(b)); return d;
}
__device__ __forceinline__ void unpack2(ull v, float& x, float& y){
    asm("mov.b64 {%0,%1}, %2;" : "=f"(x), "=f"(y) : "l"(v));
}
// 16B cp.async (.cg) — source MUST be 16B aligned
__device__ __forceinline__ void cp16(void* dst, const void* src, int src_bytes){
    uint32_t d = (uint32_t)__cvta_generic_to_shared(dst);
    asm volatile("cp.async.cg.shared.global [%0], [%1], 16, %2;"
                 :: "r"(d), "l"(src), "r"(src_bytes));
}
// 8B cp.async (.ca) — source only needs 8B alignment
__device__ __forceinline__ void cp8(void* dst, const void* src, int src_bytes){
    uint32_t d = (uint32_t)__cvta_generic_to_shared(dst);
    asm volatile("cp.async.ca.shared.global [%0], [%1], 8, %2;"
                 :: "r"(d), "l"(src), "r"(src_bytes));
}

// ---------------------------------------------------------------------------
// Kernel 1a/1b: joint-regressor precompute (partials + deterministic combine)
// ---------------------------------------------------------------------------
__global__ void __launch_bounds__(256) k_reg_part(
    const float* __restrict__ Jreg, const float* __restrict__ sdirs,
    const float* __restrict__ vt)
{
    const int jc = blockIdx.x;
    const int j = jc / 3, c = jc % 3;
    const int v0 = blockIdx.y * 862;
    const int v1 = (v0 + 862 < VN) ? v0 + 862 : VN;
    float acc[11];
#pragma unroll
    for (int l = 0; l < 11; l++) acc[l] = 0.f;
    for (int v = v0 + threadIdx.x; v < v1; v += 256){
        float r = Jreg[j*VN + v];
        const float* sd = sdirs + (v*3 + c)*10;
#pragma unroll
        for (int l = 0; l < 10; l++) acc[l] += r * __ldg(sd + l);
        acc[10] += r * vt[v*3 + c];
    }
    __shared__ float red[11][256];
#pragma unroll
    for (int l = 0; l < 11; l++) red[l][threadIdx.x] = acc[l];
    __syncthreads();
    for (int s = 128; s > 0; s >>= 1){
        if (threadIdx.x < s){
#pragma unroll
            for (int l = 0; l < 11; l++)
                red[l][threadIdx.x] += red[l][threadIdx.x + s];
        }
        __syncthreads();
    }
    if (threadIdx.x == 0){
#pragma unroll
        for (int l = 0; l < 11; l++)
            g_part[(jc*8 + blockIdx.y)*11 + l] = red[l][0];
    }
}

__global__ void k_reg_fin()
{
    int t = threadIdx.x;
    if (t < 72){
        float s[11];
#pragma unroll
        for (int l = 0; l < 11; l++) s[l] = 0.f;
        for (int q = 0; q < 8; q++)
#pragma unroll
            for (int l = 0; l < 11; l++)
                s[l] += g_part[(t*8 + q)*11 + l];
#pragma unroll
        for (int l = 0; l < 10; l++) g_JS[t*10 + l] = s[l];
        g_JT[t] = s[10];
    }
}

// ---------------------------------------------------------------------------
// Kernel 2: per-batch joints (Rodrigues, chain, A); writes pf transposed.
// ---------------------------------------------------------------------------
__global__ void __launch_bounds__(256) k_joints(
    const float* __restrict__ betas, const float* __restrict__ pose,
    const int* __restrict__ parents, float* __restrict__ out)
{
    __shared__ float sL[8][24][12];
    __shared__ float sW[8][24][12];
    __shared__ int   s_par[24];
    const int w = threadIdx.x >> 5, lane = threadIdx.x & 31;
    const int b = blockIdx.x * 8 + w;
    if (threadIdx.x < 24) s_par[threadIdx.x] = parents[threadIdx.x];
    __syncthreads();

    const int j = lane;
    float Jr0 = 0.f, Jr1 = 0.f, Jr2 = 0.f;

    if (j < JN){
        float x = pose[b*72 + j*3 + 0];
        float y = pose[b*72 + j*3 + 1];
        float z = pose[b*72 + j*3 + 2];
        float ax = x + 1e-8f, ay = y + 1e-8f, az = z + 1e-8f;
        float ang = sqrtf(ax*ax + ay*ay + az*az);
        float inv = 1.0f / ang;
        float kx = x*inv, ky = y*inv, kz = z*inv;
        float sn = sinf(ang), cs = cosf(ang);
        float oc = 1.0f - cs;
        float kk = kx*kx + ky*ky + kz*kz;
        float R[9];
        R[0] = 1.f + oc*(kx*kx - kk);  R[1] = -sn*kz + oc*kx*ky;      R[2] =  sn*ky + oc*kx*kz;
        R[3] =  sn*kz + oc*ky*kx;      R[4] = 1.f + oc*(ky*ky - kk);  R[5] = -sn*kx + oc*ky*kz;
        R[6] = -sn*ky + oc*kz*kx;      R[7] =  sn*kx + oc*kz*ky;      R[8] = 1.f + oc*(kz*kz - kk);

        float jr[3];
#pragma unroll
        for (int c = 0; c < 3; c++){
            float a = g_JT[j*3 + c];
#pragma unroll
            for (int l = 0; l < 10; l++)
                a += betas[b*10 + l] * g_JS[(j*3+c)*10 + l];
            jr[c] = a;
            out[OFF_JREST + b*JN*3 + j*3 + c] = a;
        }
        Jr0 = jr[0]; Jr1 = jr[1]; Jr2 = jr[2];

        if (j >= 1){
            // pose_feature transposed: g_pfT[k][b]
            int kb = (j-1)*9;
#pragma unroll
            for (int r = 0; r < 3; r++)
#pragma unroll
                for (int c = 0; c < 3; c++)
                    g_pfT[(kb + r*3 + c)*BN + b] = R[r*3 + c] - ((r == c) ? 1.f : 0.f);
        }
#pragma unroll
        for (int r = 0; r < 3; r++){
            sL[w][j][r*4+0] = R[r*3+0];
            sL[w][j][r*4+1] = R[r*3+1];
            sL[w][j][r*4+2] = R[r*3+2];
        }
    }

    int par = 0;
    if (j < JN && j > 0) par = s_par[j];
    float p0 = __shfl_sync(0xffffffffu, Jr0, par);
    float p1 = __shfl_sync(0xffffffffu, Jr1, par);
    float p2 = __shfl_sync(0xffffffffu, Jr2, par);
    if (j < JN){
        sL[w][j][3]  = (j == 0) ? Jr0 : Jr0 - p0;
        sL[w][j][7]  = (j == 0) ? Jr1 : Jr1 - p1;
        sL[w][j][11] = (j == 0) ? Jr2 : Jr2 - p2;
    }
    __syncwarp();

    if (lane < 12) sW[w][0][lane] = sL[w][0][lane];
    __syncwarp();
    for (int i = 1; i < JN; i++){
        if (lane < 12){
            int pi = s_par[i];
            const float* Wp = sW[w][pi];
            const float* L  = sL[w][i];
            int r = lane >> 2, cc = lane & 3;
            float val = Wp[r*4+0]*L[0*4+cc] + Wp[r*4+1]*L[1*4+cc] + Wp[r*4+2]*L[2*4+cc];
            if (cc == 3) val += Wp[r*4+3];
            sW[w][i][lane] = val;
        }
        __syncwarp();
    }

    if (j < JN){
        const float* W = sW[w][j];
#pragma unroll
        for (int r = 0; r < 3; r++)
            out[OFF_JPOSED + b*JN*3 + j*3 + r] = W[r*4+3];
        float* Ao = out + OFF_A + (b*JN + j)*16;
#pragma unroll
        for (int r = 0; r < 3; r++){
            Ao[r*4+0] = W[r*4+0]; Ao[r*4+1] = W[r*4+1]; Ao[r*4+2] = W[r*4+2];
            Ao[r*4+3] = W[r*4+3] - (W[r*4+0]*Jr0 + W[r*4+1]*Jr1 + W[r*4+2]*Jr2);
        }
        Ao[12] = 0.f; Ao[13] = 0.f; Ao[14] = 0.f; Ao[15] = 1.f;
    }
}

// ---------------------------------------------------------------------------
// Kernel 3: pose-blend GEMM (tf32 HMMA), cp.async double-buffered, K-chunk 32.
//   delta[m][n] = sum_k pdirs[k][m] * pfT[k][n]
//   A rows are only 8B-aligned (NV3*4 = 82680 ≡ 8 mod 16) -> 8B cp.async.ca.
//   B rows are 4096B-strided from an aligned table     -> 16B cp.async.cg.
//   Raw fp32 bits fed to mma.tf32 (hw truncates mantissa) — no cvt.
// ---------------------------------------------------------------------------
#define GBM 128
#define GBN 64
#define GBK 32
#define NSTEP 7          // 7*32 = 224 = KP2
#define SA_LD 136        // 136 % 32 == 8 -> conflict-free fragment loads
#define SB_LD 72
#define SA_BUF (GBK*SA_LD)
#define SB_BUF (GBK*SB_LD)
#define GEMM_SMEM ((2*SA_BUF + 2*SB_BUF)*4)

__global__ void __launch_bounds__(256) k_gemm(const float* __restrict__ pdirs)
{
    extern __shared__ float dsm[];
    float* sA = dsm;                    // [2][GBK][SA_LD]
    float* sB = dsm + 2*SA_BUF;         // [2][GBK][SB_LD]

    const int tid = threadIdx.x;
    const int warp = tid >> 5, lane = tid & 31;
    const int m0 = blockIdx.x * GBM;
    const int n0 = blockIdx.y * GBN;
    const int wm = (warp & 3) * 32;
    const int wn = (warp >> 2) * 32;
    const int g  = lane >> 2, tg = lane & 3;

    float d[2][4][4];
#pragma unroll
    for (int mt = 0; mt < 2; mt++)
#pragma unroll
        for (int nt = 0; nt < 4; nt++)
#pragma unroll
            for (int i = 0; i < 4; i++) d[mt][nt][i] = 0.f;

    // A chunk: 32 rows x 128 floats = 2048 8B-chunks (8 per thread, 8B aligned)
    // B chunk: 32 rows x  64 floats =  512 16B-chunks (2 per thread)
    auto stage = [&](int ks, int buf){
        const int k0 = ks * GBK;
        float* a = sA + buf*SA_BUF;
        float* bsh = sB + buf*SB_BUF;
#pragma unroll
        for (int i = 0; i < 8; i++){
            int c = tid + i*256;             // 0..2047
            int kk = c >> 6, c2 = (c & 63)*2;
            int gk = k0 + kk, gm = m0 + c2;
            // NV3 is even and gm is even -> an 8B chunk is either fully
            // in-bounds or fully out; no partial straddle.
            int sz = (gk < KF && gm + 1 < NV3) ? 8 : 0;
            const float* src = sz ? (pdirs + (long)gk*NV3 + gm) : pdirs;
            cp8(a + kk*SA_LD + c2, src, sz);
        }
#pragma unroll
        for (int i = 0; i < 2; i++){
            int c = tid + i*256;             // 0..511
            int kk = c >> 4, c4 = (c & 15)*4;
            cp16(bsh + kk*SB_LD + c4, g_pfT + (long)(k0 + kk)*BN + n0 + c4, 16);
        }
        asm volatile("cp.async.commit_group;");
    };

    stage(0, 0);

    for (int ks = 0; ks < NSTEP; ks++){
        const int buf = ks & 1;
        if (ks + 1 < NSTEP){
            stage(ks + 1, buf ^ 1);
            asm volatile("cp.async.wait_group 1;");
        } else {
            asm volatile("cp.async.wait_group 0;");
        }
        __syncthreads();

        const float* a = sA + buf*SA_BUF;
        const float* bsh = sB + buf*SB_BUF;
#pragma unroll
        for (int kg = 0; kg < 4; kg++){
            const int kb = kg * 8;
            uint32_t af[2][4], bf[4][2];
#pragma unroll
            for (int mt = 0; mt < 2; mt++){
                int rb = wm + mt*16 + g;
                af[mt][0] = __float_as_uint(a[(kb+tg  )*SA_LD + rb]);
                af[mt][1] = __float_as_uint(a[(kb+tg  )*SA_LD + rb + 8]);
                af[mt][2] = __float_as_uint(a[(kb+tg+4)*SA_LD + rb]);
                af[mt][3] = __float_as_uint(a[(kb+tg+4)*SA_LD + rb + 8]);
            }
#pragma unroll
            for (int nt = 0; nt < 4; nt++){
                int cb = wn + nt*8 + g;
                bf[nt][0] = __float_as_uint(bsh[(kb+tg  )*SB_LD + cb]);
                bf[nt][1] = __float_as_uint(bsh[(kb+tg+4)*SB_LD + cb]);
            }
#pragma unroll
            for (int mt = 0; mt < 2; mt++)
#pragma unroll
                for (int nt = 0; nt < 4; nt++){
                    asm volatile(
                        "mma.sync.aligned.m16n8k8.row.col.f32.tf32.tf32.f32 "
                        "{%0,%1,%2,%3}, {%4,%5,%6,%7}, {%8,%9}, {%0,%1,%2,%3};"
                        : "+f"(d[mt][nt][0]), "+f"(d[mt][nt][1]),
                          "+f"(d[mt][nt][2]), "+f"(d[mt][nt][3])
                        : "r"(af[mt][0]), "r"(af[mt][1]), "r"(af[mt][2]), "r"(af[mt][3]),
                          "r"(bf[nt][0]), "r"(bf[nt][1]));
                }
        }
        __syncthreads();
    }

    // epilogue: g_vp layout [m][1024]
#pragma unroll
    for (int mt = 0; mt < 2; mt++)
#pragma unroll
        for (int nt = 0; nt < 4; nt++){
            int r0 = m0 + wm + mt*16 + g;
            int c0 = n0 + wn + nt*8 + tg*2;
            if (r0 < NV3)
                *(float2*)(g_vp + (long)r0*BN + c0) = make_float2(d[mt][nt][0], d[mt][nt][1]);
            if (r0 + 8 < NV3)
                *(float2*)(g_vp + (long)(r0+8)*BN + c0) = make_float2(d[mt][nt][2], d[mt][nt][3]);
        }
}

// ---------------------------------------------------------------------------
// Kernel 4: vertex kernel. Block = 128 vertices x 16 batches.
// ---------------------------------------------------------------------------
__global__ void __launch_bounds__(256, 3) k_vertex(
    const float* __restrict__ betas, const float* __restrict__ vt,
    const float* __restrict__ sdirs, const float* __restrict__ lbsw,
    float* __restrict__ out)
{
    extern __shared__ char smem[];
    float (*s_A)[12][16] = (float(*)[12][16])(smem + S_A_OFF);
    float (*s_b)[16]     = (float(*)[16])(smem + S_B_OFF);
    ull   (*s_vp)[25]    = (ull(*)[25])(smem + S_VP_OFF);
    float (*s_w)[25]     = (float(*)[25])(smem + S_W_OFF);

    const int tid = threadIdx.x;
    const int b_block = blockIdx.y * 16;
    const int v_base  = blockIdx.x * 128;

    for (int idx = tid; idx < 16*JN*12; idx += 256){
        int bi = idx / 288, e = idx - bi*288;
        int j = e / 12, rc = e - j*12;
        s_A[j][rc][bi] = out[OFF_A + ((b_block + bi)*JN + j)*16 + rc];
    }
    for (int idx = tid; idx < 160; idx += 256){
        int bi = idx / 10, l = idx - bi*10;
        s_b[l][bi] = betas[(b_block + bi)*10 + l];
    }
    for (int idx = tid; idx < 128*JN; idx += 256){
        int vl = idx / JN, j = idx - vl*JN;
        int vg = v_base + vl; if (vg >= VN) vg = VN - 1;
        s_w[vl][j] = lbsw[vg*JN + j];
    }
    __syncthreads();

    // ---- phase 1 ----
    const int v_loc = tid >> 1;
    const int half  = tid & 1;
    const int bb    = half * 8;
    const int v     = v_base + v_loc;
    const bool valid = v < VN;
    const int vv = valid ? v : (VN - 1);

    ull acc[4][3];
    {
        float t0 = vt[vv*3+0], t1 = vt[vv*3+1], t2 = vt[vv*3+2];
        ull d0 = pack2(t0,t0), d1 = pack2(t1,t1), d2 = pack2(t2,t2);
#pragma unroll
        for (int p = 0; p < 4; p++){ acc[p][0]=d0; acc[p][1]=d1; acc[p][2]=d2; }
    }
    {
        const float* sd = sdirs + vv*30;
#pragma unroll
        for (int l = 0; l < 10; l++){
            float a0 = __ldg(sd + l), a1 = __ldg(sd + 10 + l), a2 = __ldg(sd + 20 + l);
            ull d0 = pack2(a0,a0), d1 = pack2(a1,a1), d2 = pack2(a2,a2);
            const ull* bl = (const ull*)&s_b[l][bb];
#pragma unroll
            for (int p = 0; p < 4; p++){
                ull bp = bl[p];
                acc[p][0] = fma2(d0, bp, acc[p][0]);
                acc[p][1] = fma2(d1, bp, acc[p][1]);
                acc[p][2] = fma2(d2, bp, acc[p][2]);
            }
        }
    }
    if (valid){
#pragma unroll
        for (int p = 0; p < 4; p++){
            int b0 = b_block + bb + 2*p;
            float x, y;
            unpack2(acc[p][0], x, y);
            out[OFF_VSH + b0*NV3 + v*3+0] = x; out[OFF_VSH + (b0+1)*NV3 + v*3+0] = y;
            unpack2(acc[p][1], x, y);
            out[OFF_VSH + b0*NV3 + v*3+1] = x; out[OFF_VSH + (b0+1)*NV3 + v*3+1] = y;
            unpack2(acc[p][2], x, y);
            out[OFF_VSH + b0*NV3 + v*3+2] = x; out[OFF_VSH + (b0+1)*NV3 + v*3+2] = y;
        }
    }

    // add pose-blend delta from tensor-core GEMM
#pragma unroll
    for (int c = 0; c < 3; c++){
        const ulonglong2* dp = (const ulonglong2*)(g_vp + ((long)vv*3 + c)*BN + b_block + bb);
        ulonglong2 q0 = __ldg(dp), q1 = __ldg(dp + 1);
        acc[0][c] = add2(acc[0][c], q0.x);
        acc[1][c] = add2(acc[1][c], q0.y);
        acc[2][c] = add2(acc[2][c], q1.x);
        acc[3][c] = add2(acc[3][c], q1.y);
    }

    // ---- handoff to smem ----
#pragma unroll
    for (int p = 0; p < 4; p++){
        int pair = half*4 + p;
        s_vp[v_loc][pair*3 + 0] = acc[p][0];
        s_vp[v_loc][pair*3 + 1] = acc[p][1];
        s_vp[v_loc][pair*3 + 2] = acc[p][2];
    }
    __syncthreads();

    // ---- phase 2: skinning ----
    const int pp = tid >> 5;
    const int l  = tid & 31;

    ull vp[4][3], vr[4][3];
#pragma unroll
    for (int i = 0; i < 4; i++){
#pragma unroll
        for (int c = 0; c < 3; c++){
            vp[i][c] = s_vp[l + 32*i][pp*3 + c];
            vr[i][c] = 0ull;
        }
    }

#pragma unroll 4
    for (int j = 0; j < JN; j++){
        ull ar[12];
#pragma unroll
        for (int rc = 0; rc < 12; rc++)
            ar[rc] = *(const ull*)&s_A[j][rc][2*pp];
#pragma unroll
        for (int i = 0; i < 4; i++){
            float wj = s_w[l + 32*i][j];
            ull w2 = pack2(wj, wj);
            ull vx = vp[i][0], vy = vp[i][1], vz = vp[i][2];
#pragma unroll
            for (int r = 0; r < 3; r++){
                ull q = fma2(ar[r*4+2], vz, ar[r*4+3]);
                q     = fma2(ar[r*4+1], vy, q);
                q     = fma2(ar[r*4+0], vx, q);
                vr[i][r] = fma2(w2, q, vr[i][r]);
            }
        }
    }

    const int b0 = b_block + 2*pp;
#pragma unroll
    for (int i = 0; i < 4; i++){
        int vg = v_base + l + 32*i;
        if (vg < VN){
            float x, y;
            unpack2(vr[i][0], x, y);
            out[OFF_VERTS + b0*NV3 + vg*3+0] = x; out[OFF_VERTS + (b0+1)*NV3 + vg*3+0] = y;
            unpack2(vr[i][1], x, y);
            out[OFF_VERTS + b0*NV3 + vg*3+1] = x; out[OFF_VERTS + (b0+1)*NV3 + vg*3+1] = y;
            unpack2(vr[i][2], x, y);
            out[OFF_VERTS + b0*NV3 + vg*3+2] = x; out[OFF_VERTS + (b0+1)*NV3 + vg*3+2] = y;
        }
    }
}

extern "C" void kernel_launch(void* const* d_in, const int* in_sizes, int n_in,
                              void* d_out, int out_size)
{
    const float* betas   = (const float*)d_in[0];
    const float* pose    = (const float*)d_in[1];
    const float* vt      = (const float*)d_in[2];
    const float* sdirs   = (const float*)d_in[3];
    const float* pdirs   = (const float*)d_in[4];
    const float* Jreg    = (const float*)d_in[5];
    const float* lbsw    = (const float*)d_in[6];
    const int*   parents = (const int*)d_in[7];
    float* out = (float*)d_out;

    cudaFuncSetAttribute(k_vertex, cudaFuncAttributeMaxDynamicSharedMemorySize, SMEM_BYTES);
    cudaFuncSetAttribute(k_gemm,   cudaFuncAttributeMaxDynamicSharedMemorySize, GEMM_SMEM);

    dim3 g1(72, 8);
    k_reg_part<<<g1, 256>>>(Jreg, sdirs, vt);
    k_reg_fin<<<1, 128>>>();
    k_joints<<<128, 256>>>(betas, pose, parents, out);
    dim3 gg((NV3 + GBM - 1)/GBM, BN/GBN);   // 162 x 16
    k_gemm<<<gg, 256, GEMM_SMEM>>>(pdirs);
    dim3 g3(54, 64);   // ceil(6890/128) x (1024/16)
    k_vertex<<<g3, 256, SMEM_BYTES>>>(betas, vt, sdirs, lbsw, out);
}